// round 4
// baseline (speedup 1.0000x reference)
#include <cuda_runtime.h>
#include <cuda_bf16.h>
#include <math.h>

// Problem constants (shapes fixed by the dataset)
#define NN 100000           // nodes
#define NE 1000000          // edges
#define ET 4                // edge types
#define DI 64               // input dim
#define DH 256              // hidden dim
#define KU (ET*DI)          // 256 = update row width
#define G3 (3*DI)           // 192 = gate width

// Scratch (device globals — allocation-free)
__device__ float g_update[(size_t)NN * KU];   // 102.4 MB
__device__ float g_hidden[(size_t)NN * DH];   // 102.4 MB
__device__ float g_gi[(size_t)NN * G3];       // 76.8 MB
__device__ float g_gh[(size_t)NN * G3];       // 76.8 MB
__device__ int   g_src[NE];
__device__ int   g_dst[NE];
__device__ int   g_typ[NE];
__device__ int   g_is_i32;                    // 1 => edge arrays are int32

// ---------------------------------------------------------------------------
// Index-dtype probe: reset flag, then read edge_index words as int64.
// If the underlying data is int32, an int64 read packs two random indices and
// is >= NN (high word nonzero) with overwhelming probability over 4096 probes.
// ---------------------------------------------------------------------------
__global__ void flag_reset_kernel() { g_is_i32 = 0; }

__global__ void probe_kernel(const long long* __restrict__ eidx) {
    int i = blockIdx.x * blockDim.x + threadIdx.x;   // 4096 probes
    long long v = eidx[i];                           // safe: 32KB < 8MB min buffer
    if (v < 0 || v >= (long long)NN) atomicExch(&g_is_i32, 1);
}

// Normalize edge indices/types to int32 scratch, whatever the source dtype.
__global__ void convert_kernel(const void* __restrict__ eidx,
                               const void* __restrict__ etype) {
    int e = blockIdx.x * blockDim.x + threadIdx.x;
    if (e >= NE) return;
    if (g_is_i32) {
        const int* p = (const int*)eidx;
        g_src[e] = p[e];
        g_dst[e] = p[NE + e];
        g_typ[e] = ((const int*)etype)[e];
    } else {
        const long long* p = (const long long*)eidx;
        g_src[e] = (int)p[e];
        g_dst[e] = (int)p[NE + e];
        g_typ[e] = (int)((const long long*)etype)[e];
    }
}

// ---------------------------------------------------------------------------
// Zero the update accumulator (float4 streaming stores)
// ---------------------------------------------------------------------------
__global__ void zero_kernel(float4* __restrict__ p, int n4) {
    int i = blockIdx.x * blockDim.x + threadIdx.x;
    if (i < n4) p[i] = make_float4(0.f, 0.f, 0.f, 0.f);
}

// ---------------------------------------------------------------------------
// Edge scatter: update[(dst*4+type)*64 + d] += w * x[src, d]
// 16 threads per edge, each owns one float4 chunk (coalesced 256B src read),
// 4 scalar f32 L2 reductions per thread. Bounds-guarded (probe safety net).
// ---------------------------------------------------------------------------
__global__ void scatter_kernel(const float* __restrict__ x,
                               const float* __restrict__ ew,
                               float* __restrict__ upd) {
    int i = blockIdx.x * blockDim.x + threadIdx.x;   // NE*16 work items
    int e = i >> 4;
    int c = i & 15;
    if (e >= NE) return;
    int src = g_src[e];
    int dst = g_dst[e];
    int t   = g_typ[e];
    if ((unsigned)src >= NN || (unsigned)dst >= NN || (unsigned)t >= ET) return;
    float w = ew[e];
    float4 v = *(const float4*)(x + (size_t)src * DI + c * 4);
    float* drow = upd + ((size_t)dst * ET + t) * DI + c * 4;
    atomicAdd(drow + 0, w * v.x);
    atomicAdd(drow + 1, w * v.y);
    atomicAdd(drow + 2, w * v.z);
    atomicAdd(drow + 3, w * v.w);
}

// ---------------------------------------------------------------------------
// SGEMM: C[M,N] = epi(A[M,K] @ B[N,K]^T + bias[N])
// BM=64, BN=64, BK=16, 256 threads, 4x4 register tile per thread.
// N multiple of 64 (256 and 192 both are). K multiple of 16.
// ---------------------------------------------------------------------------
template<int K, int RELU>
__global__ void __launch_bounds__(256) gemm_bt(const float* __restrict__ A,
                                               const float* __restrict__ B,
                                               const float* __restrict__ bias,
                                               float* __restrict__ C,
                                               int M, int N) {
    __shared__ float As[64][20];
    __shared__ float Bs[16][68];

    const int tid = threadIdx.x;
    const int tx  = tid & 15;        // n
    const int ty  = tid >> 4;        // m
    const int m0  = blockIdx.x * 64;
    const int n0  = blockIdx.y * 64;

    const int arow = tid >> 2;       // 0..63
    const int acol = (tid & 3) * 4;  // 0,4,8,12

    float acc[4][4];
#pragma unroll
    for (int r = 0; r < 4; r++)
#pragma unroll
        for (int c = 0; c < 4; c++) acc[r][c] = 0.f;

    const int ty4 = ty * 4;
    const int tx4 = tx * 4;

    for (int k0 = 0; k0 < K; k0 += 16) {
        float4 av = make_float4(0.f, 0.f, 0.f, 0.f);
        int am = m0 + arow;
        if (am < M) av = *(const float4*)(A + (size_t)am * K + k0 + acol);
        *(float4*)(&As[arow][acol]) = av;

        float4 bv = *(const float4*)(B + (size_t)(n0 + arow) * K + k0 + acol);
        Bs[acol + 0][arow] = bv.x;
        Bs[acol + 1][arow] = bv.y;
        Bs[acol + 2][arow] = bv.z;
        Bs[acol + 3][arow] = bv.w;
        __syncthreads();

#pragma unroll
        for (int k = 0; k < 16; ++k) {
            float a0 = As[ty4 + 0][k];
            float a1 = As[ty4 + 1][k];
            float a2 = As[ty4 + 2][k];
            float a3 = As[ty4 + 3][k];
            float4 b = *(const float4*)(&Bs[k][tx4]);
            acc[0][0] += a0 * b.x; acc[0][1] += a0 * b.y; acc[0][2] += a0 * b.z; acc[0][3] += a0 * b.w;
            acc[1][0] += a1 * b.x; acc[1][1] += a1 * b.y; acc[1][2] += a1 * b.z; acc[1][3] += a1 * b.w;
            acc[2][0] += a2 * b.x; acc[2][1] += a2 * b.y; acc[2][2] += a2 * b.z; acc[2][3] += a2 * b.w;
            acc[3][0] += a3 * b.x; acc[3][1] += a3 * b.y; acc[3][2] += a3 * b.z; acc[3][3] += a3 * b.w;
        }
        __syncthreads();
    }

    float4 bb = *(const float4*)(bias + n0 + tx4);
#pragma unroll
    for (int r = 0; r < 4; r++) {
        int m = m0 + ty4 + r;
        if (m < M) {
            float4 o;
            o.x = acc[r][0] + bb.x;
            o.y = acc[r][1] + bb.y;
            o.z = acc[r][2] + bb.z;
            o.w = acc[r][3] + bb.w;
            if (RELU) {
                o.x = fmaxf(o.x, 0.f);
                o.y = fmaxf(o.y, 0.f);
                o.z = fmaxf(o.z, 0.f);
                o.w = fmaxf(o.w, 0.f);
            }
            *(float4*)(C + (size_t)m * N + n0 + tx4) = o;
        }
    }
}

// ---------------------------------------------------------------------------
// GRU gate epilogue: out = (1-z)*n + z*h
// ---------------------------------------------------------------------------
__global__ void gates_kernel(const float* __restrict__ x,
                             const float* __restrict__ gi,
                             const float* __restrict__ gh,
                             float* __restrict__ out) {
    int i = blockIdx.x * blockDim.x + threadIdx.x;   // NN*DI
    if (i >= NN * DI) return;
    int m = i >> 6;
    int d = i & 63;
    const float* gim = gi + (size_t)m * G3;
    const float* ghm = gh + (size_t)m * G3;
    float ir  = gim[d],        hr = ghm[d];
    float iz  = gim[64 + d],   hz = ghm[64 + d];
    float in_ = gim[128 + d],  hn = ghm[128 + d];
    float r = 1.f / (1.f + expf(-(ir + hr)));
    float z = 1.f / (1.f + expf(-(iz + hz)));
    float n = tanhf(in_ + r * hn);
    float h = x[i];
    out[i] = (1.f - z) * n + z * h;
}

// ---------------------------------------------------------------------------
// Launch
// ---------------------------------------------------------------------------
extern "C" void kernel_launch(void* const* d_in, const int* in_sizes, int n_in,
                              void* d_out, int out_size) {
    const float* x     = (const float*)d_in[0];      // [NN, 64]
    const void*  eidx  = d_in[1];                    // [2, NE] int32 or int64
    const void*  etype = d_in[2];                    // [NE]
    const float* ew    = (const float*)d_in[3];      // [NE]
    const float* mlpW  = (const float*)d_in[4];      // [256, 256]
    const float* mlpb  = (const float*)d_in[5];      // [256]
    const float* wih   = (const float*)d_in[6];      // [192, 256]
    const float* whh   = (const float*)d_in[7];      // [192, 64]
    const float* bih   = (const float*)d_in[8];      // [192]
    const float* bhh   = (const float*)d_in[9];      // [192]
    float*       out   = (float*)d_out;              // [NN, 64]

    float *upd, *hid, *gi, *gh;
    cudaGetSymbolAddress((void**)&upd, g_update);
    cudaGetSymbolAddress((void**)&hid, g_hidden);
    cudaGetSymbolAddress((void**)&gi,  g_gi);
    cudaGetSymbolAddress((void**)&gh,  g_gh);

    const int MB = (NN + 63) / 64;

    // 0) dtype probe + index normalization
    flag_reset_kernel<<<1, 1>>>();
    probe_kernel<<<16, 256>>>((const long long*)eidx);
    convert_kernel<<<(NE + 255) / 256, 256>>>(eidx, etype);

    // 1) zero accumulator: 25.6M floats = 6.4M float4
    zero_kernel<<<25000, 256>>>((float4*)upd, 6400000);

    // 2) edge scatter
    scatter_kernel<<<(NE * 16) / 256, 256>>>(x, ew, upd);

    // 3) hidden = relu(update @ mlpW^T + mlpb)   [NN,256]
    gemm_bt<KU, 1><<<dim3(MB, DH / 64), 256>>>(upd, mlpW, mlpb, hid, NN, DH);

    // 4) gi = hidden @ w_ih^T + b_ih             [NN,192]
    gemm_bt<DH, 0><<<dim3(MB, G3 / 64), 256>>>(hid, wih, bih, gi, NN, G3);

    // 5) gh = x @ w_hh^T + b_hh                  [NN,192]
    gemm_bt<DI, 0><<<dim3(MB, G3 / 64), 256>>>(x, whh, bhh, gh, NN, G3);

    // 6) GRU gates -> out
    gates_kernel<<<(NN * DI) / 256, 256>>>(x, gi, gh, out);
}

// round 5
// speedup vs baseline: 1.1958x; 1.1958x over previous
#include <cuda_runtime.h>
#include <cuda_bf16.h>
#include <math.h>
#include <stdint.h>

// Problem constants (shapes fixed by the dataset)
#define NN 100000           // nodes
#define NE 1000000          // edges
#define ET 4                // edge types
#define DI 64               // input dim
#define DH 256              // hidden dim
#define KU (ET*DI)          // 256 = update row width
#define G3 (3*DI)           // 192 = gate width

// Scratch (device globals — allocation-free)
__device__ float g_update[(size_t)NN * KU];   // 102.4 MB
__device__ float g_hidden[(size_t)NN * DH];   // 102.4 MB
__device__ float g_gi[(size_t)NN * G3];       // 76.8 MB
__device__ float g_gh[(size_t)NN * G3];       // 76.8 MB
__device__ int   g_src[NE];
__device__ int   g_dst[NE];
__device__ int   g_typ[NE];
__device__ int   g_is_i32;                    // 1 => edge arrays are int32

// ---------------------------------------------------------------------------
// Index-dtype probe (unchanged from passing R4 kernel)
// ---------------------------------------------------------------------------
__global__ void flag_reset_kernel() { g_is_i32 = 0; }

__global__ void probe_kernel(const long long* __restrict__ eidx) {
    int i = blockIdx.x * blockDim.x + threadIdx.x;   // 4096 probes
    long long v = eidx[i];
    if (v < 0 || v >= (long long)NN) atomicExch(&g_is_i32, 1);
}

__global__ void convert_kernel(const void* __restrict__ eidx,
                               const void* __restrict__ etype) {
    int e = blockIdx.x * blockDim.x + threadIdx.x;
    if (e >= NE) return;
    if (g_is_i32) {
        const int* p = (const int*)eidx;
        g_src[e] = p[e];
        g_dst[e] = p[NE + e];
        g_typ[e] = ((const int*)etype)[e];
    } else {
        const long long* p = (const long long*)eidx;
        g_src[e] = (int)p[e];
        g_dst[e] = (int)p[NE + e];
        g_typ[e] = (int)((const long long*)etype)[e];
    }
}

// ---------------------------------------------------------------------------
// Zero the update accumulator
// ---------------------------------------------------------------------------
__global__ void zero_kernel(float4* __restrict__ p, int n4) {
    int i = blockIdx.x * blockDim.x + threadIdx.x;
    if (i < n4) p[i] = make_float4(0.f, 0.f, 0.f, 0.f);
}

// ---------------------------------------------------------------------------
// Edge scatter with vectorized L2 reduction (red.global.add.v4.f32).
// 16 threads per edge, one 16B reduction each (was 4 scalar atomics).
// ---------------------------------------------------------------------------
__global__ void scatter_kernel(const float* __restrict__ x,
                               const float* __restrict__ ew,
                               float* __restrict__ upd) {
    int i = blockIdx.x * blockDim.x + threadIdx.x;   // NE*16 work items
    int e = i >> 4;
    int c = i & 15;
    if (e >= NE) return;
    int src = g_src[e];
    int dst = g_dst[e];
    int t   = g_typ[e];
    if ((unsigned)src >= NN || (unsigned)dst >= NN || (unsigned)t >= ET) return;
    float w = ew[e];
    float4 v = *(const float4*)(x + (size_t)src * DI + c * 4);
    float* drow = upd + ((size_t)dst * ET + t) * DI + c * 4;
    asm volatile("red.global.add.v4.f32 [%0], {%1,%2,%3,%4};"
                 :: "l"(drow), "f"(w * v.x), "f"(w * v.y),
                    "f"(w * v.z), "f"(w * v.w)
                 : "memory");
}

// ---------------------------------------------------------------------------
// 3xTF32 tensor-core GEMM: C[M,N] = epi(A[M,K] @ B[N,K]^T + bias[N])
// Block 128x64, 8 warps (4x2), warp tile 32x32, BK=16.
// Each fp32 input is split a = hi + lo (both tf32); products hi*hi + hi*lo +
// lo*hi give ~fp32 accuracy (residual ~2.4e-7 relative).
// mma.sync.m16n8k8.tf32 fragments, fp32 accumulation.
// ---------------------------------------------------------------------------
__device__ __forceinline__ void tf32split(float v, float& hi, float& lo) {
    uint32_t u;
    asm("cvt.rna.tf32.f32 %0, %1;" : "=r"(u) : "f"(v));
    hi = __uint_as_float(u);
    float r = v - hi;
    uint32_t u2;
    asm("cvt.rna.tf32.f32 %0, %1;" : "=r"(u2) : "f"(r));
    lo = __uint_as_float(u2);
}

#define MMA_TF32(d, a, b0, b1)                                                 \
    asm volatile(                                                              \
        "mma.sync.aligned.m16n8k8.row.col.f32.tf32.tf32.f32 "                  \
        "{%0,%1,%2,%3},{%4,%5,%6,%7},{%8,%9},{%0,%1,%2,%3};"                   \
        : "+f"((d)[0]), "+f"((d)[1]), "+f"((d)[2]), "+f"((d)[3])               \
        : "r"((a)[0]), "r"((a)[1]), "r"((a)[2]), "r"((a)[3]),                  \
          "r"(b0), "r"(b1))

template<int K, int RELU>
__global__ void __launch_bounds__(256) gemm_tf32(const float* __restrict__ A,
                                                 const float* __restrict__ B,
                                                 const float* __restrict__ bias,
                                                 float* __restrict__ C,
                                                 int M, int N) {
    __shared__ float Ah[128][20];
    __shared__ float Al[128][20];
    __shared__ float Bh[64][20];
    __shared__ float Bl[64][20];

    const int tid  = threadIdx.x;
    const int lane = tid & 31;
    const int w    = tid >> 5;
    const int wm   = (w & 3) * 32;   // warp m offset in block
    const int wn   = (w >> 2) * 32;  // warp n offset in block
    const int m0   = blockIdx.x * 128;
    const int n0   = blockIdx.y * 64;

    const int lrow = tid >> 2;         // 0..63
    const int lcol = (tid & 3) * 4;    // 0,4,8,12

    float acc[2][4][4];
#pragma unroll
    for (int mt = 0; mt < 2; mt++)
#pragma unroll
        for (int nt = 0; nt < 4; nt++)
#pragma unroll
            for (int j = 0; j < 4; j++) acc[mt][nt][j] = 0.f;

    for (int k0 = 0; k0 < K; k0 += 16) {
        // Load + split A tile (128x16): 2 float4 per thread
#pragma unroll
        for (int p = 0; p < 2; p++) {
            int r  = p * 64 + lrow;
            int gm = m0 + r;
            float4 v = make_float4(0.f, 0.f, 0.f, 0.f);
            if (gm < M) v = *(const float4*)(A + (size_t)gm * K + k0 + lcol);
            float h, l;
            tf32split(v.x, h, l); Ah[r][lcol + 0] = h; Al[r][lcol + 0] = l;
            tf32split(v.y, h, l); Ah[r][lcol + 1] = h; Al[r][lcol + 1] = l;
            tf32split(v.z, h, l); Ah[r][lcol + 2] = h; Al[r][lcol + 2] = l;
            tf32split(v.w, h, l); Ah[r][lcol + 3] = h; Al[r][lcol + 3] = l;
        }
        // Load + split B tile (64x16): 1 float4 per thread
        {
            float4 v = *(const float4*)(B + (size_t)(n0 + lrow) * K + k0 + lcol);
            float h, l;
            tf32split(v.x, h, l); Bh[lrow][lcol + 0] = h; Bl[lrow][lcol + 0] = l;
            tf32split(v.y, h, l); Bh[lrow][lcol + 1] = h; Bl[lrow][lcol + 1] = l;
            tf32split(v.z, h, l); Bh[lrow][lcol + 2] = h; Bl[lrow][lcol + 2] = l;
            tf32split(v.w, h, l); Bh[lrow][lcol + 3] = h; Bl[lrow][lcol + 3] = l;
        }
        __syncthreads();

#pragma unroll
        for (int ks = 0; ks < 16; ks += 8) {
            // A fragments (hi and lo) for both 16-row tiles
            uint32_t ah[2][4], al[2][4];
#pragma unroll
            for (int mt = 0; mt < 2; mt++) {
                int r = wm + mt * 16 + (lane >> 2);
                int c = ks + (lane & 3);
                ah[mt][0] = __float_as_uint(Ah[r][c]);
                ah[mt][1] = __float_as_uint(Ah[r + 8][c]);
                ah[mt][2] = __float_as_uint(Ah[r][c + 4]);
                ah[mt][3] = __float_as_uint(Ah[r + 8][c + 4]);
                al[mt][0] = __float_as_uint(Al[r][c]);
                al[mt][1] = __float_as_uint(Al[r + 8][c]);
                al[mt][2] = __float_as_uint(Al[r][c + 4]);
                al[mt][3] = __float_as_uint(Al[r + 8][c + 4]);
            }
#pragma unroll
            for (int nt = 0; nt < 4; nt++) {
                int cn = wn + nt * 8 + (lane >> 2);
                int ck = ks + (lane & 3);
                uint32_t bh0 = __float_as_uint(Bh[cn][ck]);
                uint32_t bh1 = __float_as_uint(Bh[cn][ck + 4]);
                uint32_t bl0 = __float_as_uint(Bl[cn][ck]);
                uint32_t bl1 = __float_as_uint(Bl[cn][ck + 4]);
#pragma unroll
                for (int mt = 0; mt < 2; mt++) {
                    MMA_TF32(acc[mt][nt], ah[mt], bh0, bh1);  // hi*hi
                    MMA_TF32(acc[mt][nt], ah[mt], bl0, bl1);  // hi*lo
                    MMA_TF32(acc[mt][nt], al[mt], bh0, bh1);  // lo*hi
                }
            }
        }
        __syncthreads();
    }

    // Epilogue: D fragment (16x8 f32): rows lane/4 and lane/4+8,
    // cols 2*(lane&3) and +1.
#pragma unroll
    for (int mt = 0; mt < 2; mt++) {
#pragma unroll
        for (int nt = 0; nt < 4; nt++) {
            int row = m0 + wm + mt * 16 + (lane >> 2);
            int col = n0 + wn + nt * 8 + 2 * (lane & 3);
            float b0v = bias[col];
            float b1v = bias[col + 1];
            float v0 = acc[mt][nt][0] + b0v;
            float v1 = acc[mt][nt][1] + b1v;
            float v2 = acc[mt][nt][2] + b0v;
            float v3 = acc[mt][nt][3] + b1v;
            if (RELU) {
                v0 = fmaxf(v0, 0.f); v1 = fmaxf(v1, 0.f);
                v2 = fmaxf(v2, 0.f); v3 = fmaxf(v3, 0.f);
            }
            if (row < M)
                *(float2*)(C + (size_t)row * N + col) = make_float2(v0, v1);
            if (row + 8 < M)
                *(float2*)(C + (size_t)(row + 8) * N + col) = make_float2(v2, v3);
        }
    }
}

// ---------------------------------------------------------------------------
// GRU gate epilogue: out = (1-z)*n + z*h
// ---------------------------------------------------------------------------
__global__ void gates_kernel(const float* __restrict__ x,
                             const float* __restrict__ gi,
                             const float* __restrict__ gh,
                             float* __restrict__ out) {
    int i = blockIdx.x * blockDim.x + threadIdx.x;   // NN*DI
    if (i >= NN * DI) return;
    int m = i >> 6;
    int d = i & 63;
    const float* gim = gi + (size_t)m * G3;
    const float* ghm = gh + (size_t)m * G3;
    float ir  = gim[d],        hr = ghm[d];
    float iz  = gim[64 + d],   hz = ghm[64 + d];
    float in_ = gim[128 + d],  hn = ghm[128 + d];
    float r = 1.f / (1.f + expf(-(ir + hr)));
    float z = 1.f / (1.f + expf(-(iz + hz)));
    float n = tanhf(in_ + r * hn);
    float h = x[i];
    out[i] = (1.f - z) * n + z * h;
}

// ---------------------------------------------------------------------------
// Launch
// ---------------------------------------------------------------------------
extern "C" void kernel_launch(void* const* d_in, const int* in_sizes, int n_in,
                              void* d_out, int out_size) {
    const float* x     = (const float*)d_in[0];      // [NN, 64]
    const void*  eidx  = d_in[1];                    // [2, NE] int32 or int64
    const void*  etype = d_in[2];                    // [NE]
    const float* ew    = (const float*)d_in[3];      // [NE]
    const float* mlpW  = (const float*)d_in[4];      // [256, 256]
    const float* mlpb  = (const float*)d_in[5];      // [256]
    const float* wih   = (const float*)d_in[6];      // [192, 256]
    const float* whh   = (const float*)d_in[7];      // [192, 64]
    const float* bih   = (const float*)d_in[8];      // [192]
    const float* bhh   = (const float*)d_in[9];      // [192]
    float*       out   = (float*)d_out;              // [NN, 64]

    float *upd, *hid, *gi, *gh;
    cudaGetSymbolAddress((void**)&upd, g_update);
    cudaGetSymbolAddress((void**)&hid, g_hidden);
    cudaGetSymbolAddress((void**)&gi,  g_gi);
    cudaGetSymbolAddress((void**)&gh,  g_gh);

    const int MB128 = (NN + 127) / 128;   // 782

    // 0) dtype probe + index normalization
    flag_reset_kernel<<<1, 1>>>();
    probe_kernel<<<16, 256>>>((const long long*)eidx);
    convert_kernel<<<(NE + 255) / 256, 256>>>(eidx, etype);

    // 1) zero accumulator: 25.6M floats = 6.4M float4
    zero_kernel<<<25000, 256>>>((float4*)upd, 6400000);

    // 2) edge scatter (vectorized L2 reductions)
    scatter_kernel<<<(NE * 16) / 256, 256>>>(x, ew, upd);

    // 3) hidden = relu(update @ mlpW^T + mlpb)   [NN,256]
    gemm_tf32<KU, 1><<<dim3(MB128, DH / 64), 256>>>(upd, mlpW, mlpb, hid, NN, DH);

    // 4) gi = hidden @ w_ih^T + b_ih             [NN,192]
    gemm_tf32<DH, 0><<<dim3(MB128, G3 / 64), 256>>>(hid, wih, bih, gi, NN, G3);

    // 5) gh = x @ w_hh^T + b_hh                  [NN,192]
    gemm_tf32<DI, 0><<<dim3(MB128, G3 / 64), 256>>>(x, whh, bhh, gh, NN, G3);

    // 6) GRU gates -> out
    gates_kernel<<<(NN * DI) / 256, 256>>>(x, gi, gh, out);
}

// round 6
// speedup vs baseline: 2.0048x; 1.6765x over previous
#include <cuda_runtime.h>
#include <cuda_bf16.h>
#include <math.h>
#include <stdint.h>

// Problem constants (shapes fixed by the dataset)
#define NN 100000           // nodes
#define NE 1000000          // edges
#define ET 4                // edge types
#define DI 64               // input dim
#define DH 256              // hidden dim
#define KU (ET*DI)          // 256 = update row width
#define G3 (3*DI)           // 192 = gate width

// Scratch (device globals — allocation-free)
__device__ float g_update[(size_t)NN * KU];   // 102.4 MB
__device__ float g_hidden[(size_t)NN * DH];   // 102.4 MB
__device__ float g_gi[(size_t)NN * G3];       // 76.8 MB
__device__ float g_gh[(size_t)NN * G3];       // 76.8 MB
__device__ int   g_src[NE];
__device__ int   g_dst[NE];
__device__ int   g_typ[NE];
__device__ int   g_is_i32;                    // 1 => edge arrays are int32

// ---------------------------------------------------------------------------
// Index-dtype probe (unchanged — known good)
// ---------------------------------------------------------------------------
__global__ void flag_reset_kernel() { g_is_i32 = 0; }

__global__ void probe_kernel(const long long* __restrict__ eidx) {
    int i = blockIdx.x * blockDim.x + threadIdx.x;   // 4096 probes
    long long v = eidx[i];
    if (v < 0 || v >= (long long)NN) atomicExch(&g_is_i32, 1);
}

__global__ void convert_kernel(const void* __restrict__ eidx,
                               const void* __restrict__ etype) {
    int e = blockIdx.x * blockDim.x + threadIdx.x;
    if (e >= NE) return;
    if (g_is_i32) {
        const int* p = (const int*)eidx;
        g_src[e] = p[e];
        g_dst[e] = p[NE + e];
        g_typ[e] = ((const int*)etype)[e];
    } else {
        const long long* p = (const long long*)eidx;
        g_src[e] = (int)p[e];
        g_dst[e] = (int)p[NE + e];
        g_typ[e] = (int)((const long long*)etype)[e];
    }
}

// ---------------------------------------------------------------------------
// Zero the update accumulator
// ---------------------------------------------------------------------------
__global__ void zero_kernel(float4* __restrict__ p, int n4) {
    int i = blockIdx.x * blockDim.x + threadIdx.x;
    if (i < n4) p[i] = make_float4(0.f, 0.f, 0.f, 0.f);
}

// ---------------------------------------------------------------------------
// Edge scatter with vectorized L2 reduction (red.global.add.v4.f32).
// ---------------------------------------------------------------------------
__global__ void scatter_kernel(const float* __restrict__ x,
                               const float* __restrict__ ew,
                               float* __restrict__ upd) {
    int i = blockIdx.x * blockDim.x + threadIdx.x;   // NE*16 work items
    int e = i >> 4;
    int c = i & 15;
    if (e >= NE) return;
    int src = g_src[e];
    int dst = g_dst[e];
    int t   = g_typ[e];
    if ((unsigned)src >= NN || (unsigned)dst >= NN || (unsigned)t >= ET) return;
    float w = ew[e];
    float4 v = *(const float4*)(x + (size_t)src * DI + c * 4);
    float* drow = upd + ((size_t)dst * ET + t) * DI + c * 4;
    asm volatile("red.global.add.v4.f32 [%0], {%1,%2,%3,%4};"
                 :: "l"(drow), "f"(w * v.x), "f"(w * v.y),
                    "f"(w * v.z), "f"(w * v.w)
                 : "memory");
}

// ---------------------------------------------------------------------------
// Single-pass TF32 tensor-core GEMM: C[M,N] = epi(A[M,K] @ B[N,K]^T + bias[N])
// Block 128x64, 8 warps (4x2), warp tile 32x32, BK=16.
// Inputs rounded to tf32 (cvt.rna) at smem-store time; eps ~4.9e-4 per input,
// aggregate output rel err ~1e-4 (threshold 1e-3).
// ---------------------------------------------------------------------------
#define MMA_TF32(d, a, b0, b1)                                                 \
    asm volatile(                                                              \
        "mma.sync.aligned.m16n8k8.row.col.f32.tf32.tf32.f32 "                  \
        "{%0,%1,%2,%3},{%4,%5,%6,%7},{%8,%9},{%0,%1,%2,%3};"                   \
        : "+f"((d)[0]), "+f"((d)[1]), "+f"((d)[2]), "+f"((d)[3])               \
        : "r"((a)[0]), "r"((a)[1]), "r"((a)[2]), "r"((a)[3]),                  \
          "r"(b0), "r"(b1))

__device__ __forceinline__ uint32_t to_tf32(float v) {
    uint32_t u;
    asm("cvt.rna.tf32.f32 %0, %1;" : "=r"(u) : "f"(v));
    return u;
}

template<int K, int RELU>
__global__ void __launch_bounds__(256) gemm_tf32(const float* __restrict__ A,
                                                 const float* __restrict__ B,
                                                 const float* __restrict__ bias,
                                                 float* __restrict__ C,
                                                 int M, int N) {
    __shared__ uint32_t As[128][20];
    __shared__ uint32_t Bs[64][20];

    const int tid  = threadIdx.x;
    const int lane = tid & 31;
    const int w    = tid >> 5;
    const int wm   = (w & 3) * 32;   // warp m offset in block
    const int wn   = (w >> 2) * 32;  // warp n offset in block
    const int m0   = blockIdx.x * 128;
    const int n0   = blockIdx.y * 64;

    const int lrow = tid >> 2;         // 0..63
    const int lcol = (tid & 3) * 4;    // 0,4,8,12

    float acc[2][4][4];
#pragma unroll
    for (int mt = 0; mt < 2; mt++)
#pragma unroll
        for (int nt = 0; nt < 4; nt++)
#pragma unroll
            for (int j = 0; j < 4; j++) acc[mt][nt][j] = 0.f;

    for (int k0 = 0; k0 < K; k0 += 16) {
        // Load A tile (128x16): 2 float4 per thread, convert to tf32
#pragma unroll
        for (int p = 0; p < 2; p++) {
            int r  = p * 64 + lrow;
            int gm = m0 + r;
            float4 v = make_float4(0.f, 0.f, 0.f, 0.f);
            if (gm < M) v = *(const float4*)(A + (size_t)gm * K + k0 + lcol);
            As[r][lcol + 0] = to_tf32(v.x);
            As[r][lcol + 1] = to_tf32(v.y);
            As[r][lcol + 2] = to_tf32(v.z);
            As[r][lcol + 3] = to_tf32(v.w);
        }
        // Load B tile (64x16): 1 float4 per thread
        {
            float4 v = *(const float4*)(B + (size_t)(n0 + lrow) * K + k0 + lcol);
            Bs[lrow][lcol + 0] = to_tf32(v.x);
            Bs[lrow][lcol + 1] = to_tf32(v.y);
            Bs[lrow][lcol + 2] = to_tf32(v.z);
            Bs[lrow][lcol + 3] = to_tf32(v.w);
        }
        __syncthreads();

#pragma unroll
        for (int ks = 0; ks < 16; ks += 8) {
            uint32_t af[2][4];
#pragma unroll
            for (int mt = 0; mt < 2; mt++) {
                int r = wm + mt * 16 + (lane >> 2);
                int c = ks + (lane & 3);
                af[mt][0] = As[r][c];
                af[mt][1] = As[r + 8][c];
                af[mt][2] = As[r][c + 4];
                af[mt][3] = As[r + 8][c + 4];
            }
#pragma unroll
            for (int nt = 0; nt < 4; nt++) {
                int cn = wn + nt * 8 + (lane >> 2);
                int ck = ks + (lane & 3);
                uint32_t b0 = Bs[cn][ck];
                uint32_t b1 = Bs[cn][ck + 4];
                MMA_TF32(acc[0][nt], af[0], b0, b1);
                MMA_TF32(acc[1][nt], af[1], b0, b1);
            }
        }
        __syncthreads();
    }

    // Epilogue
#pragma unroll
    for (int mt = 0; mt < 2; mt++) {
#pragma unroll
        for (int nt = 0; nt < 4; nt++) {
            int row = m0 + wm + mt * 16 + (lane >> 2);
            int col = n0 + wn + nt * 8 + 2 * (lane & 3);
            float b0v = bias[col];
            float b1v = bias[col + 1];
            float v0 = acc[mt][nt][0] + b0v;
            float v1 = acc[mt][nt][1] + b1v;
            float v2 = acc[mt][nt][2] + b0v;
            float v3 = acc[mt][nt][3] + b1v;
            if (RELU) {
                v0 = fmaxf(v0, 0.f); v1 = fmaxf(v1, 0.f);
                v2 = fmaxf(v2, 0.f); v3 = fmaxf(v3, 0.f);
            }
            if (row < M)
                *(float2*)(C + (size_t)row * N + col) = make_float2(v0, v1);
            if (row + 8 < M)
                *(float2*)(C + (size_t)(row + 8) * N + col) = make_float2(v2, v3);
        }
    }
}

// ---------------------------------------------------------------------------
// GRU gate epilogue: out = (1-z)*n + z*h
// ---------------------------------------------------------------------------
__global__ void gates_kernel(const float* __restrict__ x,
                             const float* __restrict__ gi,
                             const float* __restrict__ gh,
                             float* __restrict__ out) {
    int i = blockIdx.x * blockDim.x + threadIdx.x;   // NN*DI
    if (i >= NN * DI) return;
    int m = i >> 6;
    int d = i & 63;
    const float* gim = gi + (size_t)m * G3;
    const float* ghm = gh + (size_t)m * G3;
    float ir  = gim[d],        hr = ghm[d];
    float iz  = gim[64 + d],   hz = ghm[64 + d];
    float in_ = gim[128 + d],  hn = ghm[128 + d];
    float r = 1.f / (1.f + expf(-(ir + hr)));
    float z = 1.f / (1.f + expf(-(iz + hz)));
    float n = tanhf(in_ + r * hn);
    float h = x[i];
    out[i] = (1.f - z) * n + z * h;
}

// ---------------------------------------------------------------------------
// Launch
// ---------------------------------------------------------------------------
extern "C" void kernel_launch(void* const* d_in, const int* in_sizes, int n_in,
                              void* d_out, int out_size) {
    const float* x     = (const float*)d_in[0];      // [NN, 64]
    const void*  eidx  = d_in[1];                    // [2, NE] int32 or int64
    const void*  etype = d_in[2];                    // [NE]
    const float* ew    = (const float*)d_in[3];      // [NE]
    const float* mlpW  = (const float*)d_in[4];      // [256, 256]
    const float* mlpb  = (const float*)d_in[5];      // [256]
    const float* wih   = (const float*)d_in[6];      // [192, 256]
    const float* whh   = (const float*)d_in[7];      // [192, 64]
    const float* bih   = (const float*)d_in[8];      // [192]
    const float* bhh   = (const float*)d_in[9];      // [192]
    float*       out   = (float*)d_out;              // [NN, 64]

    float *upd, *hid, *gi, *gh;
    cudaGetSymbolAddress((void**)&upd, g_update);
    cudaGetSymbolAddress((void**)&hid, g_hidden);
    cudaGetSymbolAddress((void**)&gi,  g_gi);
    cudaGetSymbolAddress((void**)&gh,  g_gh);

    const int MB128 = (NN + 127) / 128;   // 782

    // 0) dtype probe + index normalization
    flag_reset_kernel<<<1, 1>>>();
    probe_kernel<<<16, 256>>>((const long long*)eidx);
    convert_kernel<<<(NE + 255) / 256, 256>>>(eidx, etype);

    // 1) zero accumulator
    zero_kernel<<<25000, 256>>>((float4*)upd, 6400000);

    // 2) edge scatter (vectorized L2 reductions)
    scatter_kernel<<<(NE * 16) / 256, 256>>>(x, ew, upd);

    // 3) hidden = relu(update @ mlpW^T + mlpb)   [NN,256]
    gemm_tf32<KU, 1><<<dim3(MB128, DH / 64), 256>>>(upd, mlpW, mlpb, hid, NN, DH);

    // 4) gi = hidden @ w_ih^T + b_ih             [NN,192]
    gemm_tf32<DH, 0><<<dim3(MB128, G3 / 64), 256>>>(hid, wih, bih, gi, NN, G3);

    // 5) gh = x @ w_hh^T + b_hh                  [NN,192]
    gemm_tf32<DI, 0><<<dim3(MB128, G3 / 64), 256>>>(x, whh, bhh, gh, NN, G3);

    // 6) GRU gates -> out
    gates_kernel<<<(NN * DI) / 256, 256>>>(x, gi, gh, out);
}